// round 16
// baseline (speedup 1.0000x reference)
#include <cuda_runtime.h>
#include <cuda_bf16.h>
#include <cuda_fp16.h>
#include <cstdint>

// Problem constants
#define B_   16384
#define DIN  1024
#define D_   512
#define K_   8192
#define KP2  3072          // gemm1 packed K: [a0|a0|a1] . [b0|b1|b0]

#define MARGIN2 0.16f      // bf16 noise (0.08) + packed-score quantization slack @ bias 48
#define CAP     32
#define BIAS    48.0f

// ---------------------------------------------------------------------------
// Scratch (device globals; allocations forbidden)
// ---------------------------------------------------------------------------
__device__ float  g_ze[(size_t)B_ * D_];     // z_e fp32
__device__ float  g_c2[K_];                  // |c|^2 (exact, for rescore)
__device__ float  g_c2b[K_];                 // |c|^2 + BIAS (for phase1 keys)
__device__ int    g_idx[B_];
__device__ uint2  g_top[(size_t)8 * B_ * 16];      // per-(xblk,row,slot) packed top-2, 16MB
__device__ __nv_bfloat16 g_xs[(size_t)B_ * KP2];   // packed x splits
__device__ __nv_bfloat16 g_ws[(size_t)D_ * KP2];   // packed W splits
__device__ __nv_bfloat16 g_zb[(size_t)B_ * D_];    // bf16(z_e)
__device__ __nv_bfloat16 g_cbb[(size_t)K_ * D_];   // bf16(cb)

// ---------------------------------------------------------------------------
// PTX helpers (baseline PTX only: works at .target sm_100)
// ---------------------------------------------------------------------------
__device__ __forceinline__ uint32_t smem_u32(const void* p) {
    uint32_t a;
    asm("{ .reg .u64 t; cvta.to.shared.u64 t, %1; cvt.u32.u64 %0, t; }" : "=r"(a) : "l"(p));
    return a;
}
__device__ __forceinline__ void cp_async16(uint32_t saddr, const void* gaddr) {
    asm volatile("cp.async.cg.shared.global [%0], [%1], 16;" :: "r"(saddr), "l"(gaddr));
}
__device__ __forceinline__ void cp_commit() { asm volatile("cp.async.commit_group;"); }
__device__ __forceinline__ void cp_wait1()  { asm volatile("cp.async.wait_group 1;" ::: "memory"); }

__device__ __forceinline__ void ldsm_x4(uint32_t& r0, uint32_t& r1, uint32_t& r2, uint32_t& r3,
                                        uint32_t addr) {
    asm volatile("ldmatrix.sync.aligned.m8n8.x4.shared.b16 {%0,%1,%2,%3}, [%4];"
                 : "=r"(r0), "=r"(r1), "=r"(r2), "=r"(r3) : "r"(addr));
}
__device__ __forceinline__ void mma_bf16(float* c, const uint32_t* a, uint32_t b0, uint32_t b1) {
    asm volatile("mma.sync.aligned.m16n8k16.row.col.f32.bf16.bf16.f32 "
                 "{%0,%1,%2,%3}, {%4,%5,%6,%7}, {%8,%9}, {%0,%1,%2,%3};"
                 : "+f"(c[0]), "+f"(c[1]), "+f"(c[2]), "+f"(c[3])
                 : "r"(a[0]), "r"(a[1]), "r"(a[2]), "r"(a[3]), "r"(b0), "r"(b1));
}

// Swizzles:
// A-resident (phase1): 1024B rows, 64 x 16B chunks, XOR within 8-chunk groups
#define SWA(r, c) ((r) * 1024 + ((((c) & 0x38) | (((c) & 7) ^ ((r) & 7))) << 4))
// 128B-row stage tiles (BLK_K=64 bf16): 8 x 16B chunks, XOR by row
#define SWB(r, c) ((r) * 128 + ((((c) ^ ((r) & 7)) & 7) << 4))

// ---------------------------------------------------------------------------
// Merged prep kernel (one launch):
//   blocks [0, B_)            : pack x row  -> g_xs  [a0|a0|a1]
//   blocks [B_, B_+D_)        : pack W row  -> g_ws  [b0|b1|b0]
//   blocks [B_+D_, +K_/8)     : codebook c2/c2b + bf16 pack (8 rows/block)
// ---------------------------------------------------------------------------
__global__ void prep_kernel(const float* __restrict__ x, const float* __restrict__ w,
                            const float* __restrict__ cb) {
    const int b = blockIdx.x, t = threadIdx.x;

    if (b < B_ + D_) {
        const bool isx = (b < B_);
        const int row = isx ? b : (b - B_);
        const float* src = isx ? x : w;

        float4 v = *reinterpret_cast<const float4*>(src + (size_t)row * DIN + t * 4);
        __nv_bfloat162 h01, h23, l01, l23;
        h01.x = __float2bfloat16_rn(v.x); h01.y = __float2bfloat16_rn(v.y);
        h23.x = __float2bfloat16_rn(v.z); h23.y = __float2bfloat16_rn(v.w);
        l01.x = __float2bfloat16_rn(v.x - __bfloat162float(h01.x));
        l01.y = __float2bfloat16_rn(v.y - __bfloat162float(h01.y));
        l23.x = __float2bfloat16_rn(v.z - __bfloat162float(h23.x));
        l23.y = __float2bfloat16_rn(v.w - __bfloat162float(h23.y));

        if (isx) {
            __nv_bfloat162* d = reinterpret_cast<__nv_bfloat162*>(g_xs + (size_t)row * KP2 + t * 4);
            d[0] = h01; d[1] = h23;
            d += 512;  d[0] = h01; d[1] = h23;
            d += 512;  d[0] = l01; d[1] = l23;
        } else {
            __nv_bfloat162* d = reinterpret_cast<__nv_bfloat162*>(g_ws + (size_t)row * KP2 + t * 4);
            d[0] = h01; d[1] = h23;
            d += 512;  d[0] = l01; d[1] = l23;
            d += 512;  d[0] = h01; d[1] = h23;
        }
    } else {
        const int row  = (b - B_ - D_) * 8 + (t >> 5);
        const int lane = t & 31;
        const float4* src = reinterpret_cast<const float4*>(cb + (size_t)row * D_);
        __nv_bfloat162* dst = reinterpret_cast<__nv_bfloat162*>(g_cbb + (size_t)row * D_);
        float s = 0.f;
        #pragma unroll
        for (int j = 0; j < 4; j++) {
            const int i = lane + j * 32;
            float4 v = src[i];
            s += v.x * v.x + v.y * v.y + v.z * v.z + v.w * v.w;
            __nv_bfloat162 h0, h1;
            h0.x = __float2bfloat16_rn(v.x); h0.y = __float2bfloat16_rn(v.y);
            h1.x = __float2bfloat16_rn(v.z); h1.y = __float2bfloat16_rn(v.w);
            dst[i * 2]     = h0;
            dst[i * 2 + 1] = h1;
        }
        #pragma unroll
        for (int o = 16; o; o >>= 1) s += __shfl_xor_sync(0xffffffffu, s, o);
        if (lane == 0) { g_c2[row] = s; g_c2b[row] = s + BIAS; }
    }
}

// ---------------------------------------------------------------------------
// GEMM1 via mma.sync: z_e = x @ W^T with packed 3-split (K''=3072).
// 128-thread CTAs, M-tile 64, 3 CTAs/SM (72KB smem/CTA). BLK_K=64, 3-stage.
// grid (4, 256). Epilogue also emits bf16(z_e). UNCHANGED (at ~78% roofline).
// ---------------------------------------------------------------------------
#define G1_SA   8192                 // A stage bytes (64 x 128B)
#define G1_SB   16384                // B stage bytes (128 x 128B)
#define G1_BOFF (3 * G1_SA)          // 24576
#define SM1TOT  (3 * G1_SA + 3 * G1_SB)   // 73728 per CTA -> 3/SM

__global__ __launch_bounds__(128, 3) void gemm1_mma_kernel() {
    extern __shared__ char sm[];
    const uint32_t sbase = smem_u32(sm);
    const int tid  = threadIdx.x;
    const int lane = tid & 31;
    const int warp_n = tid >> 5;       // 0..3
    const int row0 = blockIdx.y * 64;
    const int col0 = blockIdx.x * 128;
    const int NKIT = KP2 / 64;         // 48

    const __nv_bfloat16* gA = g_xs + (size_t)row0 * KP2;
    const __nv_bfloat16* gB = g_ws + (size_t)col0 * KP2;

    float acc[4][4][4];
    #pragma unroll
    for (int mf = 0; mf < 4; mf++)
        #pragma unroll
        for (int nf = 0; nf < 4; nf++)
            #pragma unroll
            for (int q = 0; q < 4; q++) acc[mf][nf][q] = 0.f;

    #define G1_ISSUE(stg, kit) do {                                               \
        const uint32_t As_ = sbase + (stg) * G1_SA;                               \
        const uint32_t Bs_ = sbase + G1_BOFF + (stg) * G1_SB;                     \
        const int koff_ = (kit) * 64;                                             \
        _Pragma("unroll")                                                          \
        for (int i_ = 0; i_ < 4; i_++) {                                           \
            int id_ = tid + i_ * 128;                                              \
            int r_  = id_ >> 3;                                                    \
            int c_  = id_ & 7;                                                     \
            cp_async16(As_ + SWB(r_, c_), gA + (size_t)r_ * KP2 + koff_ + c_ * 8); \
        }                                                                          \
        _Pragma("unroll")                                                          \
        for (int i_ = 0; i_ < 8; i_++) {                                           \
            int id_ = tid + i_ * 128;                                              \
            int r_  = id_ >> 3;                                                    \
            int c_  = id_ & 7;                                                     \
            cp_async16(Bs_ + SWB(r_, c_), gB + (size_t)r_ * KP2 + koff_ + c_ * 8); \
        }                                                                          \
    } while (0)

    G1_ISSUE(0, 0); cp_commit();
    G1_ISSUE(1, 1); cp_commit();

    const int g = lane >> 3;
    const int r8 = lane & 7;

    for (int kit = 0; kit < NKIT; kit++) {
        cp_wait1();
        __syncthreads();
        if (kit + 2 < NKIT) G1_ISSUE((kit + 2) % 3, kit + 2);
        cp_commit();

        const int stg = kit % 3;
        const uint32_t Abase = sbase + stg * G1_SA;
        const uint32_t Bbase = sbase + G1_BOFF + stg * G1_SB;

        #pragma unroll
        for (int ks = 0; ks < 4; ks++) {
            uint32_t afr[4][4];
            #pragma unroll
            for (int mf = 0; mf < 4; mf++) {
                int rr = mf * 16 + ((g & 1) << 3) + r8;
                int ch = 2 * ks + (g >> 1);
                ldsm_x4(afr[mf][0], afr[mf][1], afr[mf][2], afr[mf][3],
                        Abase + SWB(rr, ch));
            }
            uint32_t bfr[2][4];
            #pragma unroll
            for (int nf2 = 0; nf2 < 2; nf2++) {
                int rr = warp_n * 32 + nf2 * 16 + ((g >> 1) << 3) + r8;
                int ch = 2 * ks + (g & 1);
                ldsm_x4(bfr[nf2][0], bfr[nf2][1], bfr[nf2][2], bfr[nf2][3],
                        Bbase + SWB(rr, ch));
            }
            #pragma unroll
            for (int mf = 0; mf < 4; mf++)
                #pragma unroll
                for (int nf = 0; nf < 4; nf++)
                    mma_bf16(acc[mf][nf], afr[mf],
                             bfr[nf >> 1][(nf & 1) * 2], bfr[nf >> 1][(nf & 1) * 2 + 1]);
        }
    }
    #undef G1_ISSUE

    #pragma unroll
    for (int mf = 0; mf < 4; mf++)
        #pragma unroll
        for (int h = 0; h < 2; h++) {
            const int row = row0 + mf * 16 + h * 8 + (lane >> 2);
            #pragma unroll
            for (int nf = 0; nf < 4; nf++) {
                const int col = col0 + warp_n * 32 + nf * 8 + (lane & 3) * 2;
                float2 o; o.x = acc[mf][nf][h * 2]; o.y = acc[mf][nf][h * 2 + 1];
                *reinterpret_cast<float2*>(g_ze + (size_t)row * D_ + col) = o;
                __nv_bfloat162 hb;
                hb.x = __float2bfloat16_rn(o.x); hb.y = __float2bfloat16_rn(o.y);
                *reinterpret_cast<__nv_bfloat162*>(g_zb + (size_t)row * D_ + col) = hb;
            }
        }
}

// ---------------------------------------------------------------------------
// Phase 1: single-pass bf16 approx GEMM with packed sortable-uint top-2.
// Score key u = (bits(c2b - 2*dot) & 0xFFFFE000) | code; bias 48 keeps the
// value strictly positive (no clamp needed: score<0 requires a ~30-sigma
// bf16 dot error). Top-2 update = 3 IMNMX. 128-thread CTAs, M-tile 64,
// 2 CTAs/SM. A resident (64KB), B streamed 16KB x 3. grid (8, 256).
// ---------------------------------------------------------------------------
#define P1_SM_A  0
#define P1_SM_B  65536
#define P1_SB    16384
#define P1_SMTOT (65536 + 3 * P1_SB)   // 114688 per CTA -> 2/SM

__global__ __launch_bounds__(128, 2) void phase1_kernel() {
    extern __shared__ char sm[];
    const uint32_t sbase = smem_u32(sm);
    const int tid  = threadIdx.x;
    const int lane = tid & 31;
    const int warp_n = tid >> 5;       // 0..3
    const int row0 = blockIdx.y * 64;
    const int code_base = blockIdx.x * 1024;

    // resident A: 64 rows x 64 chunks(16B)
    {
        const __nv_bfloat16* gA = g_zb + (size_t)row0 * D_;
        #pragma unroll
        for (int i = 0; i < 32; i++) {
            int idx = tid + i * 128;
            int r   = idx >> 6;
            int c16 = idx & 63;
            cp_async16(sbase + P1_SM_A + SWA(r, c16), gA + (size_t)r * D_ + c16 * 8);
        }
    }
    cp_commit();

    #define P1_ISSUE(stg, u) do {                                                  \
        const uint32_t Bs_ = sbase + P1_SM_B + (stg) * P1_SB;                      \
        const int nt_ = (u) >> 3, kit_ = (u) & 7;                                  \
        const __nv_bfloat16* gB_ = g_cbb + (size_t)(code_base + nt_ * 128) * D_;   \
        _Pragma("unroll")                                                          \
        for (int i_ = 0; i_ < 8; i_++) {                                           \
            int id_ = tid + i_ * 128;                                              \
            int r_  = id_ >> 3;                                                    \
            int c_  = id_ & 7;                                                     \
            cp_async16(Bs_ + SWB(r_, c_),                                          \
                       gB_ + (size_t)r_ * D_ + kit_ * 64 + c_ * 8);                \
        }                                                                          \
    } while (0)

    P1_ISSUE(0, 0); cp_commit();
    P1_ISSUE(1, 1); cp_commit();

    const int g = lane >> 3;
    const int r8 = lane & 7;
    float acc[4][4][4];

    uint32_t tv1[8], tv2[8];
    #pragma unroll
    for (int i = 0; i < 8; i++) { tv1[i] = 0xFFFFFFFFu; tv2[i] = 0xFFFFFFFFu; }

    #define TOP2U(u, r) do {                                                       \
        const uint32_t mx_ = max(tv1[r], (u));                                     \
        tv1[r] = min(tv1[r], (u));                                                 \
        tv2[r] = min(tv2[r], mx_);                                                 \
    } while (0)

    for (int u = 0; u < 64; u++) {
        const int nt = u >> 3, kit = u & 7;
        cp_wait1();
        __syncthreads();
        if (u + 2 < 64) P1_ISSUE((u + 2) % 3, u + 2);
        cp_commit();

        if (kit == 0) {
            #pragma unroll
            for (int mf = 0; mf < 4; mf++)
                #pragma unroll
                for (int nf = 0; nf < 4; nf++)
                    #pragma unroll
                    for (int q = 0; q < 4; q++) acc[mf][nf][q] = 0.f;
        }

        const uint32_t Bbase = sbase + P1_SM_B + (u % 3) * P1_SB;
        #pragma unroll
        for (int ks = 0; ks < 4; ks++) {
            uint32_t afr[4][4];
            #pragma unroll
            for (int mf = 0; mf < 4; mf++) {
                int rr  = mf * 16 + ((g & 1) << 3) + r8;
                int c16 = kit * 8 + 2 * ks + (g >> 1);
                ldsm_x4(afr[mf][0], afr[mf][1], afr[mf][2], afr[mf][3],
                        sbase + P1_SM_A + SWA(rr, c16));
            }
            uint32_t bfr[2][4];
            #pragma unroll
            for (int nf2 = 0; nf2 < 2; nf2++) {
                int rr = warp_n * 32 + nf2 * 16 + ((g >> 1) << 3) + r8;
                int ch = 2 * ks + (g & 1);
                ldsm_x4(bfr[nf2][0], bfr[nf2][1], bfr[nf2][2], bfr[nf2][3],
                        Bbase + SWB(rr, ch));
            }
            #pragma unroll
            for (int mf = 0; mf < 4; mf++)
                #pragma unroll
                for (int nf = 0; nf < 4; nf++)
                    mma_bf16(acc[mf][nf], afr[mf],
                             bfr[nf >> 1][(nf & 1) * 2], bfr[nf >> 1][(nf & 1) * 2 + 1]);
        }

        if (kit == 7) {   // tile done: pack + fold into top-2 (all branchless)
            #pragma unroll
            for (int nf = 0; nf < 4; nf++) {
                const int code0 = code_base + nt * 128 + warp_n * 32 + nf * 8 + (lane & 3) * 2;
                const float2 c2p = __ldg(reinterpret_cast<const float2*>(&g_c2b[code0]));
                #pragma unroll
                for (int mf = 0; mf < 4; mf++)
                    #pragma unroll
                    for (int h = 0; h < 2; h++) {
                        const int ridx = mf * 2 + h;
                        float v0 = fmaf(-2.0f, acc[mf][nf][h * 2 + 0], c2p.x);
                        float v1 = fmaf(-2.0f, acc[mf][nf][h * 2 + 1], c2p.y);
                        uint32_t u0 = (__float_as_uint(v0) & 0xFFFFE000u) | (uint32_t)code0;
                        uint32_t u1 = (__float_as_uint(v1) & 0xFFFFE000u) | (uint32_t)(code0 + 1);
                        TOP2U(u0, ridx);
                        TOP2U(u1, ridx);
                    }
            }
        }
    }
    #undef P1_ISSUE
    #undef TOP2U

    const int slot = warp_n * 4 + (lane & 3);
    #pragma unroll
    for (int ridx = 0; ridx < 8; ridx++) {
        const int mf = ridx >> 1, h = ridx & 1;
        const int row = row0 + mf * 16 + h * 8 + (lane >> 2);
        uint2 v; v.x = tv1[ridx]; v.y = tv2[ridx];
        g_top[((size_t)blockIdx.x * B_ + row) * 16 + slot] = v;
    }
}

// ---------------------------------------------------------------------------
// Phase 2 (fused zz + output): read 128 packed owners/row, gmin via umin,
// candidates = keys < bits(gmin_f+margin), index = key & 0x1FFF; exact fp64
// rescore (reference-grid fp32 rounding + lowest-index tie-break); writes
// z_q_st row, index, vq_loss. 1 warp per row.
// ---------------------------------------------------------------------------
__global__ __launch_bounds__(256) void phase2_kernel(const float* __restrict__ cb,
                                                     float* __restrict__ out) {
    __shared__ int s_cnt[8];
    __shared__ int s_list[8][CAP];
    const int wid  = threadIdx.x >> 5;
    const int lane = threadIdx.x & 31;
    const int row  = blockIdx.x * 8 + wid;

    const float* ze = g_ze + (size_t)row * D_;
    float er[16];
    double zs = 0.0;
    #pragma unroll
    for (int j = 0; j < 16; j++) {
        er[j] = ze[lane + j * 32];
        double v = (double)er[j];
        zs += v * v;
    }
    #pragma unroll
    for (int o = 16; o; o >>= 1) zs += __shfl_xor_sync(0xffffffffu, zs, o);
    const float zz = (float)zs;

    uint2 own[4];
    uint32_t gmin = 0xFFFFFFFFu;
    #pragma unroll
    for (int j = 0; j < 4; j++) {
        const int o = lane * 4 + j;
        const int xblk = o >> 4, slot = o & 15;
        own[j] = g_top[((size_t)xblk * B_ + row) * 16 + slot];
        gmin = min(gmin, own[j].x);
    }
    #pragma unroll
    for (int o = 16; o; o >>= 1)
        gmin = min(gmin, (uint32_t)__shfl_xor_sync(0xffffffffu, gmin, o));
    const uint32_t thr = __float_as_uint(__uint_as_float(gmin) + MARGIN2);

    if (lane == 0) s_cnt[wid] = 0;
    __syncwarp();
    #pragma unroll
    for (int j = 0; j < 4; j++) {
        if (own[j].x < thr) {
            int p = atomicAdd(&s_cnt[wid], 1);
            if (p < CAP) s_list[wid][p] = (int)(own[j].x & 0x1FFFu);
        }
        if (own[j].y < thr) {
            int p = atomicAdd(&s_cnt[wid], 1);
            if (p < CAP) s_list[wid][p] = (int)(own[j].y & 0x1FFFu);
        }
    }
    __syncwarp();
    const int ncand = s_cnt[wid];

    float bv = 3.4e38f;
    int   bi = 0x7fffffff;

    if (ncand <= CAP) {
        for (int c = 0; c < ncand; c++) {
            const int k = s_list[wid][c];
            const float* cr = cb + (size_t)k * D_;
            double d = 0.0;
            #pragma unroll
            for (int j = 0; j < 16; j++)
                d = fma((double)er[j], (double)cr[lane + j * 32], d);
            #pragma unroll
            for (int o = 16; o; o >>= 1) d += __shfl_xor_sync(0xffffffffu, d, o);
            float t = __fadd_rn(zz, -2.0f * (float)d);
            float v = __fadd_rn(t, g_c2[k]);
            if (v < bv || (v == bv && k < bi)) { bv = v; bi = k; }
        }
    } else {
        for (int k = 0; k < K_; k++) {
            const float* cr = cb + (size_t)k * D_;
            double d = 0.0;
            #pragma unroll
            for (int j = 0; j < 16; j++)
                d = fma((double)er[j], (double)cr[lane + j * 32], d);
            #pragma unroll
            for (int o = 16; o; o >>= 1) d += __shfl_xor_sync(0xffffffffu, d, o);
            float t = __fadd_rn(zz, -2.0f * (float)d);
            float v = __fadd_rn(t, g_c2[k]);
            if (v < bv || (v == bv && k < bi)) { bv = v; bi = k; }
        }
    }
    bi = __shfl_sync(0xffffffffu, bi, 0);

    const float* zq = cb + (size_t)bi * D_;
    float* o = out + (size_t)row * D_;
    float s = 0.f;
    #pragma unroll
    for (int j = 0; j < 16; j++) {
        const int d = lane + j * 32;
        float e    = er[j];
        float q    = zq[d];
        float diff = q - e;
        o[d] = e + diff;
        s += diff * diff;
    }
    #pragma unroll
    for (int off = 16; off; off >>= 1) s += __shfl_xor_sync(0xffffffffu, s, off);
    if (lane == 0) {
        g_idx[row] = bi;
        out[(size_t)B_ * D_ + row]      = (float)bi;
        out[(size_t)B_ * D_ + B_ + row] = s / (float)D_;
    }
}

// ---------------------------------------------------------------------------
extern "C" void kernel_launch(void* const* d_in, const int* in_sizes, int n_in,
                              void* d_out, int out_size) {
    const float* x  = (const float*)d_in[0];
    const float* W  = (const float*)d_in[1];
    const float* cb = (const float*)d_in[2];
    float* out = (float*)d_out;
    (void)in_sizes; (void)n_in; (void)out_size;

    cudaFuncSetAttribute(gemm1_mma_kernel, cudaFuncAttributeMaxDynamicSharedMemorySize, SM1TOT);
    cudaFuncSetAttribute(phase1_kernel,    cudaFuncAttributeMaxDynamicSharedMemorySize, P1_SMTOT);

    prep_kernel<<<B_ + D_ + K_ / 8, 256>>>(x, W, cb);
    gemm1_mma_kernel<<<dim3(4, 256), 128, SM1TOT>>>();
    phase1_kernel<<<dim3(8, 256), 128, P1_SMTOT>>>();
    phase2_kernel<<<B_ / 8, 256>>>(cb, out);
}

// round 17
// speedup vs baseline: 1.0190x; 1.0190x over previous
#include <cuda_runtime.h>
#include <cuda_bf16.h>
#include <cuda_fp16.h>
#include <cstdint>

// Problem constants
#define B_   16384
#define DIN  1024
#define D_   512
#define K_   8192
#define KPS  2048          // stored packed K: [p0 | p1] (hi, lo splits)

#define MARGIN2 0.16f      // bf16 noise (0.08) + packed-score quantization slack @ bias 48
#define CAP     32
#define BIAS    48.0f

// ---------------------------------------------------------------------------
// Scratch (device globals; allocations forbidden)
// ---------------------------------------------------------------------------
__device__ float  g_ze[(size_t)B_ * D_];     // z_e fp32
__device__ float  g_c2[K_];                  // |c|^2 (exact, for rescore)
__device__ float  g_c2b[K_];                 // |c|^2 + BIAS (for phase1 keys)
__device__ int    g_idx[B_];
__device__ uint2  g_top[(size_t)8 * B_ * 16];      // per-(xblk,row,slot) packed top-2, 16MB
__device__ __nv_bfloat16 g_xs[(size_t)B_ * KPS];   // x splits [a0|a1], 64MB
__device__ __nv_bfloat16 g_ws[(size_t)D_ * KPS];   // W splits [b0|b1], 2MB
__device__ __nv_bfloat16 g_zb[(size_t)B_ * D_];    // bf16(z_e)
__device__ __nv_bfloat16 g_cbb[(size_t)K_ * D_];   // bf16(cb)

// ---------------------------------------------------------------------------
// PTX helpers (baseline PTX only: works at .target sm_100)
// ---------------------------------------------------------------------------
__device__ __forceinline__ uint32_t smem_u32(const void* p) {
    uint32_t a;
    asm("{ .reg .u64 t; cvta.to.shared.u64 t, %1; cvt.u32.u64 %0, t; }" : "=r"(a) : "l"(p));
    return a;
}
__device__ __forceinline__ void cp_async16(uint32_t saddr, const void* gaddr) {
    asm volatile("cp.async.cg.shared.global [%0], [%1], 16;" :: "r"(saddr), "l"(gaddr));
}
__device__ __forceinline__ void cp_commit() { asm volatile("cp.async.commit_group;"); }
__device__ __forceinline__ void cp_wait1()  { asm volatile("cp.async.wait_group 1;" ::: "memory"); }

__device__ __forceinline__ void ldsm_x4(uint32_t& r0, uint32_t& r1, uint32_t& r2, uint32_t& r3,
                                        uint32_t addr) {
    asm volatile("ldmatrix.sync.aligned.m8n8.x4.shared.b16 {%0,%1,%2,%3}, [%4];"
                 : "=r"(r0), "=r"(r1), "=r"(r2), "=r"(r3) : "r"(addr));
}
__device__ __forceinline__ void mma_bf16(float* c, const uint32_t* a, uint32_t b0, uint32_t b1) {
    asm volatile("mma.sync.aligned.m16n8k16.row.col.f32.bf16.bf16.f32 "
                 "{%0,%1,%2,%3}, {%4,%5,%6,%7}, {%8,%9}, {%0,%1,%2,%3};"
                 : "+f"(c[0]), "+f"(c[1]), "+f"(c[2]), "+f"(c[3])
                 : "r"(a[0]), "r"(a[1]), "r"(a[2]), "r"(a[3]), "r"(b0), "r"(b1));
}

// Swizzles:
// A-resident (phase1): 1024B rows, 64 x 16B chunks, XOR within 8-chunk groups
#define SWA(r, c) ((r) * 1024 + ((((c) & 0x38) | (((c) & 7) ^ ((r) & 7))) << 4))
// 128B-row stage tiles (BLK_K=64 bf16): 8 x 16B chunks, XOR by row
#define SWB(r, c) ((r) * 128 + ((((c) ^ ((r) & 7)) & 7) << 4))

// ---------------------------------------------------------------------------
// Merged prep kernel (one launch):
//   blocks [0, B_)        : pack x row  -> g_xs  [a0|a1]
//   blocks [B_, B_+D_)    : pack W row  -> g_ws  [b0|b1]
//   blocks [B_+D_, +K_/8) : codebook c2/c2b + bf16 pack (8 rows/block)
// ---------------------------------------------------------------------------
__global__ void prep_kernel(const float* __restrict__ x, const float* __restrict__ w,
                            const float* __restrict__ cb) {
    const int b = blockIdx.x, t = threadIdx.x;

    if (b < B_ + D_) {
        const bool isx = (b < B_);
        const int row = isx ? b : (b - B_);
        const float* src = isx ? x : w;

        float4 v = *reinterpret_cast<const float4*>(src + (size_t)row * DIN + t * 4);
        __nv_bfloat162 h01, h23, l01, l23;
        h01.x = __float2bfloat16_rn(v.x); h01.y = __float2bfloat16_rn(v.y);
        h23.x = __float2bfloat16_rn(v.z); h23.y = __float2bfloat16_rn(v.w);
        l01.x = __float2bfloat16_rn(v.x - __bfloat162float(h01.x));
        l01.y = __float2bfloat16_rn(v.y - __bfloat162float(h01.y));
        l23.x = __float2bfloat16_rn(v.z - __bfloat162float(h23.x));
        l23.y = __float2bfloat16_rn(v.w - __bfloat162float(h23.y));

        __nv_bfloat16* base = isx ? (g_xs + (size_t)row * KPS)
                                  : (g_ws + (size_t)row * KPS);
        __nv_bfloat162* d = reinterpret_cast<__nv_bfloat162*>(base + t * 4);
        d[0] = h01; d[1] = h23;            // hi split at [0, 1024)
        d += 512;  d[0] = l01; d[1] = l23; // lo split at [1024, 2048)
    } else {
        const int row  = (b - B_ - D_) * 8 + (t >> 5);
        const int lane = t & 31;
        const float4* src = reinterpret_cast<const float4*>(cb + (size_t)row * D_);
        __nv_bfloat162* dst = reinterpret_cast<__nv_bfloat162*>(g_cbb + (size_t)row * D_);
        float s = 0.f;
        #pragma unroll
        for (int j = 0; j < 4; j++) {
            const int i = lane + j * 32;
            float4 v = src[i];
            s += v.x * v.x + v.y * v.y + v.z * v.z + v.w * v.w;
            __nv_bfloat162 h0, h1;
            h0.x = __float2bfloat16_rn(v.x); h0.y = __float2bfloat16_rn(v.y);
            h1.x = __float2bfloat16_rn(v.z); h1.y = __float2bfloat16_rn(v.w);
            dst[i * 2]     = h0;
            dst[i * 2 + 1] = h1;
        }
        #pragma unroll
        for (int o = 16; o; o >>= 1) s += __shfl_xor_sync(0xffffffffu, s, o);
        if (lane == 0) { g_c2[row] = s; g_c2b[row] = s + BIAS; }
    }
}

// ---------------------------------------------------------------------------
// GEMM1 via mma.sync: z_e = x @ W^T, 3-pass split GEMM over virtual K''=3072:
//   v in [0,16):  a0 . b0     v in [16,32): a0 . b1     v in [32,48): a1 . b0
// Operands stored ONCE as [p0|p1]; the loader maps virtual kit -> offsets.
// 128-thread CTAs, M-tile 64, 3 CTAs/SM. BLK_K=64, 3-stage. grid (4, 256).
// Epilogue also emits bf16(z_e). Accumulation order identical to before.
// ---------------------------------------------------------------------------
#define G1_SA   8192                 // A stage bytes (64 x 128B)
#define G1_SB   16384                // B stage bytes (128 x 128B)
#define G1_BOFF (3 * G1_SA)          // 24576
#define SM1TOT  (3 * G1_SA + 3 * G1_SB)   // 73728 per CTA -> 3/SM
#define NVKIT   48

__global__ __launch_bounds__(128, 3) void gemm1_mma_kernel() {
    extern __shared__ char sm[];
    const uint32_t sbase = smem_u32(sm);
    const int tid  = threadIdx.x;
    const int lane = tid & 31;
    const int warp_n = tid >> 5;       // 0..3
    const int row0 = blockIdx.y * 64;
    const int col0 = blockIdx.x * 128;

    const __nv_bfloat16* gA = g_xs + (size_t)row0 * KPS;
    const __nv_bfloat16* gB = g_ws + (size_t)col0 * KPS;

    float acc[4][4][4];
    #pragma unroll
    for (int mf = 0; mf < 4; mf++)
        #pragma unroll
        for (int nf = 0; nf < 4; nf++)
            #pragma unroll
            for (int q = 0; q < 4; q++) acc[mf][nf][q] = 0.f;

    // virtual kit -> stored column offsets
    #define G1_KOFF_A(v) ((v) < 16 ? (v) * 64 : ((v) < 32 ? ((v) - 16) * 64 : 1024 + ((v) - 32) * 64))
    #define G1_KOFF_B(v) ((v) < 16 ? (v) * 64 : ((v) < 32 ? 1024 + ((v) - 16) * 64 : ((v) - 32) * 64))

    #define G1_ISSUE(stg, kit) do {                                               \
        const uint32_t As_ = sbase + (stg) * G1_SA;                               \
        const uint32_t Bs_ = sbase + G1_BOFF + (stg) * G1_SB;                     \
        const int ka_ = G1_KOFF_A(kit);                                           \
        const int kb_ = G1_KOFF_B(kit);                                           \
        _Pragma("unroll")                                                          \
        for (int i_ = 0; i_ < 4; i_++) {                                           \
            int id_ = tid + i_ * 128;                                              \
            int r_  = id_ >> 3;                                                    \
            int c_  = id_ & 7;                                                     \
            cp_async16(As_ + SWB(r_, c_), gA + (size_t)r_ * KPS + ka_ + c_ * 8);  \
        }                                                                          \
        _Pragma("unroll")                                                          \
        for (int i_ = 0; i_ < 8; i_++) {                                           \
            int id_ = tid + i_ * 128;                                              \
            int r_  = id_ >> 3;                                                    \
            int c_  = id_ & 7;                                                     \
            cp_async16(Bs_ + SWB(r_, c_), gB + (size_t)r_ * KPS + kb_ + c_ * 8);  \
        }                                                                          \
    } while (0)

    G1_ISSUE(0, 0); cp_commit();
    G1_ISSUE(1, 1); cp_commit();

    const int g = lane >> 3;
    const int r8 = lane & 7;

    for (int kit = 0; kit < NVKIT; kit++) {
        cp_wait1();
        __syncthreads();
        if (kit + 2 < NVKIT) G1_ISSUE((kit + 2) % 3, kit + 2);
        cp_commit();

        const int stg = kit % 3;
        const uint32_t Abase = sbase + stg * G1_SA;
        const uint32_t Bbase = sbase + G1_BOFF + stg * G1_SB;

        #pragma unroll
        for (int ks = 0; ks < 4; ks++) {
            uint32_t afr[4][4];
            #pragma unroll
            for (int mf = 0; mf < 4; mf++) {
                int rr = mf * 16 + ((g & 1) << 3) + r8;
                int ch = 2 * ks + (g >> 1);
                ldsm_x4(afr[mf][0], afr[mf][1], afr[mf][2], afr[mf][3],
                        Abase + SWB(rr, ch));
            }
            uint32_t bfr[2][4];
            #pragma unroll
            for (int nf2 = 0; nf2 < 2; nf2++) {
                int rr = warp_n * 32 + nf2 * 16 + ((g >> 1) << 3) + r8;
                int ch = 2 * ks + (g & 1);
                ldsm_x4(bfr[nf2][0], bfr[nf2][1], bfr[nf2][2], bfr[nf2][3],
                        Bbase + SWB(rr, ch));
            }
            #pragma unroll
            for (int mf = 0; mf < 4; mf++)
                #pragma unroll
                for (int nf = 0; nf < 4; nf++)
                    mma_bf16(acc[mf][nf], afr[mf],
                             bfr[nf >> 1][(nf & 1) * 2], bfr[nf >> 1][(nf & 1) * 2 + 1]);
        }
    }
    #undef G1_ISSUE
    #undef G1_KOFF_A
    #undef G1_KOFF_B

    #pragma unroll
    for (int mf = 0; mf < 4; mf++)
        #pragma unroll
        for (int h = 0; h < 2; h++) {
            const int row = row0 + mf * 16 + h * 8 + (lane >> 2);
            #pragma unroll
            for (int nf = 0; nf < 4; nf++) {
                const int col = col0 + warp_n * 32 + nf * 8 + (lane & 3) * 2;
                float2 o; o.x = acc[mf][nf][h * 2]; o.y = acc[mf][nf][h * 2 + 1];
                *reinterpret_cast<float2*>(g_ze + (size_t)row * D_ + col) = o;
                __nv_bfloat162 hb;
                hb.x = __float2bfloat16_rn(o.x); hb.y = __float2bfloat16_rn(o.y);
                *reinterpret_cast<__nv_bfloat162*>(g_zb + (size_t)row * D_ + col) = hb;
            }
        }
}

// ---------------------------------------------------------------------------
// Phase 1: single-pass bf16 approx GEMM with packed sortable-uint top-2.
// Score key u = (bits(c2b - 2*dot) & 0xFFFFE000) | code; bias 48 keeps the
// value strictly positive. Top-2 update = 3 IMNMX. 128-thread CTAs, M-tile
// 64, 2 CTAs/SM. A resident (64KB), B streamed 16KB x 3. grid (8, 256).
// UNCHANGED from round 16.
// ---------------------------------------------------------------------------
#define P1_SM_A  0
#define P1_SM_B  65536
#define P1_SB    16384
#define P1_SMTOT (65536 + 3 * P1_SB)   // 114688 per CTA -> 2/SM

__global__ __launch_bounds__(128, 2) void phase1_kernel() {
    extern __shared__ char sm[];
    const uint32_t sbase = smem_u32(sm);
    const int tid  = threadIdx.x;
    const int lane = tid & 31;
    const int warp_n = tid >> 5;       // 0..3
    const int row0 = blockIdx.y * 64;
    const int code_base = blockIdx.x * 1024;

    // resident A: 64 rows x 64 chunks(16B)
    {
        const __nv_bfloat16* gA = g_zb + (size_t)row0 * D_;
        #pragma unroll
        for (int i = 0; i < 32; i++) {
            int idx = tid + i * 128;
            int r   = idx >> 6;
            int c16 = idx & 63;
            cp_async16(sbase + P1_SM_A + SWA(r, c16), gA + (size_t)r * D_ + c16 * 8);
        }
    }
    cp_commit();

    #define P1_ISSUE(stg, u) do {                                                  \
        const uint32_t Bs_ = sbase + P1_SM_B + (stg) * P1_SB;                      \
        const int nt_ = (u) >> 3, kit_ = (u) & 7;                                  \
        const __nv_bfloat16* gB_ = g_cbb + (size_t)(code_base + nt_ * 128) * D_;   \
        _Pragma("unroll")                                                          \
        for (int i_ = 0; i_ < 8; i_++) {                                           \
            int id_ = tid + i_ * 128;                                              \
            int r_  = id_ >> 3;                                                    \
            int c_  = id_ & 7;                                                     \
            cp_async16(Bs_ + SWB(r_, c_),                                          \
                       gB_ + (size_t)r_ * D_ + kit_ * 64 + c_ * 8);                \
        }                                                                          \
    } while (0)

    P1_ISSUE(0, 0); cp_commit();
    P1_ISSUE(1, 1); cp_commit();

    const int g = lane >> 3;
    const int r8 = lane & 7;
    float acc[4][4][4];

    uint32_t tv1[8], tv2[8];
    #pragma unroll
    for (int i = 0; i < 8; i++) { tv1[i] = 0xFFFFFFFFu; tv2[i] = 0xFFFFFFFFu; }

    #define TOP2U(u, r) do {                                                       \
        const uint32_t mx_ = max(tv1[r], (u));                                     \
        tv1[r] = min(tv1[r], (u));                                                 \
        tv2[r] = min(tv2[r], mx_);                                                 \
    } while (0)

    for (int u = 0; u < 64; u++) {
        const int nt = u >> 3, kit = u & 7;
        cp_wait1();
        __syncthreads();
        if (u + 2 < 64) P1_ISSUE((u + 2) % 3, u + 2);
        cp_commit();

        if (kit == 0) {
            #pragma unroll
            for (int mf = 0; mf < 4; mf++)
                #pragma unroll
                for (int nf = 0; nf < 4; nf++)
                    #pragma unroll
                    for (int q = 0; q < 4; q++) acc[mf][nf][q] = 0.f;
        }

        const uint32_t Bbase = sbase + P1_SM_B + (u % 3) * P1_SB;
        #pragma unroll
        for (int ks = 0; ks < 4; ks++) {
            uint32_t afr[4][4];
            #pragma unroll
            for (int mf = 0; mf < 4; mf++) {
                int rr  = mf * 16 + ((g & 1) << 3) + r8;
                int c16 = kit * 8 + 2 * ks + (g >> 1);
                ldsm_x4(afr[mf][0], afr[mf][1], afr[mf][2], afr[mf][3],
                        sbase + P1_SM_A + SWA(rr, c16));
            }
            uint32_t bfr[2][4];
            #pragma unroll
            for (int nf2 = 0; nf2 < 2; nf2++) {
                int rr = warp_n * 32 + nf2 * 16 + ((g >> 1) << 3) + r8;
                int ch = 2 * ks + (g & 1);
                ldsm_x4(bfr[nf2][0], bfr[nf2][1], bfr[nf2][2], bfr[nf2][3],
                        Bbase + SWB(rr, ch));
            }
            #pragma unroll
            for (int mf = 0; mf < 4; mf++)
                #pragma unroll
                for (int nf = 0; nf < 4; nf++)
                    mma_bf16(acc[mf][nf], afr[mf],
                             bfr[nf >> 1][(nf & 1) * 2], bfr[nf >> 1][(nf & 1) * 2 + 1]);
        }

        if (kit == 7) {   // tile done: pack + fold into top-2 (all branchless)
            #pragma unroll
            for (int nf = 0; nf < 4; nf++) {
                const int code0 = code_base + nt * 128 + warp_n * 32 + nf * 8 + (lane & 3) * 2;
                const float2 c2p = __ldg(reinterpret_cast<const float2*>(&g_c2b[code0]));
                #pragma unroll
                for (int mf = 0; mf < 4; mf++)
                    #pragma unroll
                    for (int h = 0; h < 2; h++) {
                        const int ridx = mf * 2 + h;
                        float v0 = fmaf(-2.0f, acc[mf][nf][h * 2 + 0], c2p.x);
                        float v1 = fmaf(-2.0f, acc[mf][nf][h * 2 + 1], c2p.y);
                        uint32_t u0 = (__float_as_uint(v0) & 0xFFFFE000u) | (uint32_t)code0;
                        uint32_t u1 = (__float_as_uint(v1) & 0xFFFFE000u) | (uint32_t)(code0 + 1);
                        TOP2U(u0, ridx);
                        TOP2U(u1, ridx);
                    }
            }
        }
    }
    #undef P1_ISSUE
    #undef TOP2U

    const int slot = warp_n * 4 + (lane & 3);
    #pragma unroll
    for (int ridx = 0; ridx < 8; ridx++) {
        const int mf = ridx >> 1, h = ridx & 1;
        const int row = row0 + mf * 16 + h * 8 + (lane >> 2);
        uint2 v; v.x = tv1[ridx]; v.y = tv2[ridx];
        g_top[((size_t)blockIdx.x * B_ + row) * 16 + slot] = v;
    }
}

// ---------------------------------------------------------------------------
// Phase 2 (fused zz + output): read 128 packed owners/row, gmin via umin,
// candidates = keys < bits(gmin_f+margin), index = key & 0x1FFF; exact fp64
// rescore (reference-grid fp32 rounding + lowest-index tie-break); writes
// z_q_st row, index, vq_loss. 1 warp per row. UNCHANGED from round 16.
// ---------------------------------------------------------------------------
__global__ __launch_bounds__(256) void phase2_kernel(const float* __restrict__ cb,
                                                     float* __restrict__ out) {
    __shared__ int s_cnt[8];
    __shared__ int s_list[8][CAP];
    const int wid  = threadIdx.x >> 5;
    const int lane = threadIdx.x & 31;
    const int row  = blockIdx.x * 8 + wid;

    const float* ze = g_ze + (size_t)row * D_;
    float er[16];
    double zs = 0.0;
    #pragma unroll
    for (int j = 0; j < 16; j++) {
        er[j] = ze[lane + j * 32];
        double v = (double)er[j];
        zs += v * v;
    }
    #pragma unroll
    for (int o = 16; o; o >>= 1) zs += __shfl_xor_sync(0xffffffffu, zs, o);
    const float zz = (float)zs;

    uint2 own[4];
    uint32_t gmin = 0xFFFFFFFFu;
    #pragma unroll
    for (int j = 0; j < 4; j++) {
        const int o = lane * 4 + j;
        const int xblk = o >> 4, slot = o & 15;
        own[j] = g_top[((size_t)xblk * B_ + row) * 16 + slot];
        gmin = min(gmin, own[j].x);
    }
    #pragma unroll
    for (int o = 16; o; o >>= 1)
        gmin = min(gmin, (uint32_t)__shfl_xor_sync(0xffffffffu, gmin, o));
    const uint32_t thr = __float_as_uint(__uint_as_float(gmin) + MARGIN2);

    if (lane == 0) s_cnt[wid] = 0;
    __syncwarp();
    #pragma unroll
    for (int j = 0; j < 4; j++) {
        if (own[j].x < thr) {
            int p = atomicAdd(&s_cnt[wid], 1);
            if (p < CAP) s_list[wid][p] = (int)(own[j].x & 0x1FFFu);
        }
        if (own[j].y < thr) {
            int p = atomicAdd(&s_cnt[wid], 1);
            if (p < CAP) s_list[wid][p] = (int)(own[j].y & 0x1FFFu);
        }
    }
    __syncwarp();
    const int ncand = s_cnt[wid];

    float bv = 3.4e38f;
    int   bi = 0x7fffffff;

    if (ncand <= CAP) {
        for (int c = 0; c < ncand; c++) {
            const int k = s_list[wid][c];
            const float* cr = cb + (size_t)k * D_;
            double d = 0.0;
            #pragma unroll
            for (int j = 0; j < 16; j++)
                d = fma((double)er[j], (double)cr[lane + j * 32], d);
            #pragma unroll
            for (int o = 16; o; o >>= 1) d += __shfl_xor_sync(0xffffffffu, d, o);
            float t = __fadd_rn(zz, -2.0f * (float)d);
            float v = __fadd_rn(t, g_c2[k]);
            if (v < bv || (v == bv && k < bi)) { bv = v; bi = k; }
        }
    } else {
        for (int k = 0; k < K_; k++) {
            const float* cr = cb + (size_t)k * D_;
            double d = 0.0;
            #pragma unroll
            for (int j = 0; j < 16; j++)
                d = fma((double)er[j], (double)cr[lane + j * 32], d);
            #pragma unroll
            for (int o = 16; o; o >>= 1) d += __shfl_xor_sync(0xffffffffu, d, o);
            float t = __fadd_rn(zz, -2.0f * (float)d);
            float v = __fadd_rn(t, g_c2[k]);
            if (v < bv || (v == bv && k < bi)) { bv = v; bi = k; }
        }
    }
    bi = __shfl_sync(0xffffffffu, bi, 0);

    const float* zq = cb + (size_t)bi * D_;
    float* o = out + (size_t)row * D_;
    float s = 0.f;
    #pragma unroll
    for (int j = 0; j < 16; j++) {
        const int d = lane + j * 32;
        float e    = er[j];
        float q    = zq[d];
        float diff = q - e;
        o[d] = e + diff;
        s += diff * diff;
    }
    #pragma unroll
    for (int off = 16; off; off >>= 1) s += __shfl_xor_sync(0xffffffffu, s, off);
    if (lane == 0) {
        g_idx[row] = bi;
        out[(size_t)B_ * D_ + row]      = (float)bi;
        out[(size_t)B_ * D_ + B_ + row] = s / (float)D_;
    }
}

// ---------------------------------------------------------------------------
extern "C" void kernel_launch(void* const* d_in, const int* in_sizes, int n_in,
                              void* d_out, int out_size) {
    const float* x  = (const float*)d_in[0];
    const float* W  = (const float*)d_in[1];
    const float* cb = (const float*)d_in[2];
    float* out = (float*)d_out;
    (void)in_sizes; (void)n_in; (void)out_size;

    cudaFuncSetAttribute(gemm1_mma_kernel, cudaFuncAttributeMaxDynamicSharedMemorySize, SM1TOT);
    cudaFuncSetAttribute(phase1_kernel,    cudaFuncAttributeMaxDynamicSharedMemorySize, P1_SMTOT);

    prep_kernel<<<B_ + D_ + K_ / 8, 256>>>(x, W, cb);
    gemm1_mma_kernel<<<dim3(4, 256), 128, SM1TOT>>>();
    phase1_kernel<<<dim3(8, 256), 128, P1_SMTOT>>>();
    phase2_kernel<<<B_ / 8, 256>>>(cb, out);
}